// round 2
// baseline (speedup 1.0000x reference)
#include <cuda_runtime.h>
#include <math.h>

// ---------------- problem constants ----------------
#define HDIM   1024
#define NH     16
#define HD     64
#define INTER  2048
#define NE     8
#define SEQ    1024
#define NBATCH 4
#define NTOK   4096          // NBATCH*SEQ
#define TQKV   3072          // (NH + 2*NKV)*HD
#define SLOTS  8192          // NTOK * TOPK

// ---------------- scratch (static device globals; no allocation) ----------------
__device__ float g_hn[(size_t)NTOK * HDIM];              // rmsnorm1 out
__device__ float g_qkv[(size_t)NTOK * TQKV];             // qkv proj
__device__ float g_attn[(size_t)NTOK * HDIM];            // attention out (pre o-proj)
__device__ float g_hf[(size_t)NTOK * HDIM];              // rmsnorm2 out
__device__ float g_xg[(size_t)(SLOTS + 128) * HDIM];     // gathered tokens (padded rows)
__device__ float g_gu[(size_t)SLOTS * 2 * INTER];        // gate_up output
__device__ float g_act[(size_t)(SLOTS + 128) * INTER];   // silu(g)*u (padded rows)
__device__ float g_dn[(size_t)SLOTS * HDIM];             // down proj per-slot
__device__ int   g_cnt[NE];
__device__ int   g_off[NE];
__device__ int   g_cur[NE];
__device__ int   g_tok_e[NTOK * 2];
__device__ int   g_tok_slot[NTOK * 2];
__device__ float g_tok_w[NTOK * 2];

// ---------------- small kernels ----------------
__global__ void zero_kernel() {
    if (threadIdx.x < NE) g_cnt[threadIdx.x] = 0;
}

// one block per token, 256 threads, 1 float4 each
__global__ void rmsnorm_kernel(const float* __restrict__ x,
                               const float* __restrict__ w,
                               float* __restrict__ y) {
    int t = blockIdx.x, tid = threadIdx.x;
    const float4 v = ((const float4*)(x + (size_t)t * HDIM))[tid];
    float ss = v.x * v.x + v.y * v.y + v.z * v.z + v.w * v.w;
    __shared__ float red[8];
    #pragma unroll
    for (int o = 16; o; o >>= 1) ss += __shfl_xor_sync(0xffffffffu, ss, o);
    if ((tid & 31) == 0) red[tid >> 5] = ss;
    __syncthreads();
    if (tid < 8) {
        float s2 = red[tid];
        #pragma unroll
        for (int o = 4; o; o >>= 1) s2 += __shfl_xor_sync(0xffu, s2, o);
        if (tid == 0) red[0] = s2;
    }
    __syncthreads();
    float inv = rsqrtf(red[0] * (1.0f / HDIM) + 1e-6f);
    const float4 wv = ((const float4*)w)[tid];
    float4 r = make_float4(v.x * inv * wv.x, v.y * inv * wv.y,
                           v.z * inv * wv.z, v.w * inv * wv.w);
    ((float4*)(y + (size_t)t * HDIM))[tid] = r;
}

// ---------------- SGEMM 128x128x8, 8x8 per thread, 256 threads ----------------
#define BM 128
#define BN 128
#define BKC 8

__device__ __forceinline__ void sgemm_body(
    const float* __restrict__ A, const float* __restrict__ B, float* __restrict__ C,
    int N, int K, int Meff, const float* __restrict__ res)
{
    __shared__ float As[BKC][BM];
    __shared__ float Bs[BKC][BN];
    const int tid = threadIdx.x;
    const int bx = blockIdx.x, by = blockIdx.y;
    const int aRow = tid >> 1;
    const int aCol = (tid & 1) << 2;
    const int bRow = tid >> 5;
    const int bCol = (tid & 31) << 2;
    const int tx = tid & 15, ty = tid >> 4;

    const float* Ap = A + (size_t)(by * BM + aRow) * K + aCol;
    const float* Bp = B + (size_t)bRow * N + bx * BN + bCol;

    float acc[8][8];
    #pragma unroll
    for (int i = 0; i < 8; i++)
        #pragma unroll
        for (int j = 0; j < 8; j++) acc[i][j] = 0.0f;

    for (int k0 = 0; k0 < K; k0 += BKC) {
        float4 a4 = *(const float4*)Ap;
        float4 b4 = *(const float4*)Bp;
        As[aCol + 0][aRow] = a4.x;
        As[aCol + 1][aRow] = a4.y;
        As[aCol + 2][aRow] = a4.z;
        As[aCol + 3][aRow] = a4.w;
        *(float4*)(&Bs[bRow][bCol]) = b4;
        __syncthreads();
        #pragma unroll
        for (int kk = 0; kk < BKC; kk++) {
            float ar[8], br[8];
            *(float4*)(ar)     = *(const float4*)(&As[kk][ty * 4]);
            *(float4*)(ar + 4) = *(const float4*)(&As[kk][ty * 4 + 64]);
            *(float4*)(br)     = *(const float4*)(&Bs[kk][tx * 4]);
            *(float4*)(br + 4) = *(const float4*)(&Bs[kk][tx * 4 + 64]);
            #pragma unroll
            for (int i = 0; i < 8; i++)
                #pragma unroll
                for (int j = 0; j < 8; j++)
                    acc[i][j] = fmaf(ar[i], br[j], acc[i][j]);
        }
        __syncthreads();
        Ap += BKC;
        Bp += (size_t)BKC * N;
    }

    #pragma unroll
    for (int i = 0; i < 8; i++) {
        int r = by * BM + ty * 4 + ((i < 4) ? i : (64 + i - 4));
        if (r >= Meff) continue;
        #pragma unroll
        for (int jh = 0; jh < 2; jh++) {
            int c = bx * BN + tx * 4 + jh * 64;
            float4 v = make_float4(acc[i][jh * 4 + 0], acc[i][jh * 4 + 1],
                                   acc[i][jh * 4 + 2], acc[i][jh * 4 + 3]);
            if (res) {
                const float4 rv = *(const float4*)(res + (size_t)r * N + c);
                v.x += rv.x; v.y += rv.y; v.z += rv.z; v.w += rv.w;
            }
            *(float4*)(C + (size_t)r * N + c) = v;
        }
    }
}

__global__ void sgemm_plain(const float* __restrict__ A, const float* __restrict__ B,
                            float* __restrict__ C, int N, int K,
                            const float* __restrict__ res) {
    sgemm_body(A, B, C, N, K, 1 << 30, res);
}

// batched expert GEMM: blockIdx.z = expert; rows start at g_off[e], count g_cnt[e]
__global__ void sgemm_moe(const float* __restrict__ A0, const float* __restrict__ B0,
                          float* __restrict__ C0, int N, int K, long long strideB) {
    int e = blockIdx.z;
    int Meff = g_cnt[e];
    if ((int)blockIdx.y * BM >= Meff) return;
    int off = g_off[e];
    const float* A = A0 + (size_t)off * K;
    const float* B = B0 + (size_t)e * strideB;
    float* C = C0 + (size_t)off * N;
    sgemm_body(A, B, C, N, K, Meff, nullptr);
}

// ---------------- flash attention (fp32) ----------------
// grid: (SEQ/64, NBATCH*NH). block: 256 (16x16). 64q x 64k tiles, HD=64.
#define ATTN_SMEM ((64*64 + 64*65 + 64*68 + 64*68) * 4)

__global__ void attn_kernel(const float* __restrict__ qkv,
                            const float* __restrict__ mask,
                            float* __restrict__ out) {
    extern __shared__ float sm[];
    float* Qs = sm;                 // [64][64]
    float* Kt = Qs + 64 * 64;       // [64 d][65]  (d-major)
    float* Vs = Kt + 64 * 65;       // [64 kv][68]
    float* Ps = Vs + 64 * 68;       // [64 q][68]

    const int tid = threadIdx.x;
    const int qb = blockIdx.x;
    const int bh = blockIdx.y;
    const int b = bh >> 4, h = bh & 15;
    const int s0 = qb * 64;
    const int tx = tid & 15, ty = tid >> 4;

    // load + pre-scale Q (1/sqrt(64) = 0.125)
    for (int idx = tid; idx < 64 * 16; idx += 256) {
        int r = idx >> 4, c4 = (idx & 15) << 2;
        float4 v = *(const float4*)(qkv + (size_t)(b * SEQ + s0 + r) * TQKV + h * HD + c4);
        v.x *= 0.125f; v.y *= 0.125f; v.z *= 0.125f; v.w *= 0.125f;
        *(float4*)(Qs + r * 64 + c4) = v;
    }

    float m[4], l[4], o[4][4];
    #pragma unroll
    for (int i = 0; i < 4; i++) {
        m[i] = -3.0e38f; l[i] = 0.0f;
        #pragma unroll
        for (int j = 0; j < 4; j++) o[i][j] = 0.0f;
    }

    for (int kt = 0; kt < SEQ / 64; kt++) {
        __syncthreads();   // previous tile's Ps/Vs reads done; Q load done (iter 0)
        const int k0 = kt * 64;
        for (int idx = tid; idx < 64 * 16; idx += 256) {
            int r = idx >> 4, c4 = (idx & 15) << 2;
            const float* src = qkv + (size_t)(b * SEQ + k0 + r) * TQKV + NH * HD + h * HD + c4;
            float4 kv = *(const float4*)src;
            Kt[(c4 + 0) * 65 + r] = kv.x;
            Kt[(c4 + 1) * 65 + r] = kv.y;
            Kt[(c4 + 2) * 65 + r] = kv.z;
            Kt[(c4 + 3) * 65 + r] = kv.w;
            float4 vv = *(const float4*)(src + NH * HD);   // v block is +1024 after k start
            *(float4*)(Vs + r * 68 + c4) = vv;
        }
        __syncthreads();

        // scores: rows ty*4+i, cols tx*4+j, init with mask
        float sv[4][4];
        #pragma unroll
        for (int i = 0; i < 4; i++) {
            float4 mk = *(const float4*)(mask + (size_t)(s0 + ty * 4 + i) * SEQ + k0 + tx * 4);
            sv[i][0] = mk.x; sv[i][1] = mk.y; sv[i][2] = mk.z; sv[i][3] = mk.w;
        }
        #pragma unroll 8
        for (int kk = 0; kk < 64; kk++) {
            float qf[4], kf[4];
            #pragma unroll
            for (int i = 0; i < 4; i++) qf[i] = Qs[(ty * 4 + i) * 64 + kk];
            #pragma unroll
            for (int j = 0; j < 4; j++) kf[j] = Kt[kk * 65 + tx * 4 + j];
            #pragma unroll
            for (int i = 0; i < 4; i++)
                #pragma unroll
                for (int j = 0; j < 4; j++)
                    sv[i][j] = fmaf(qf[i], kf[j], sv[i][j]);
        }

        // online softmax per row (reduce over 16-lane tx groups)
        #pragma unroll
        for (int i = 0; i < 4; i++) {
            float tm = fmaxf(fmaxf(sv[i][0], sv[i][1]), fmaxf(sv[i][2], sv[i][3]));
            #pragma unroll
            for (int off = 1; off < 16; off <<= 1)
                tm = fmaxf(tm, __shfl_xor_sync(0xffffffffu, tm, off));
            float mn = fmaxf(m[i], tm);
            float corr = __expf(m[i] - mn);
            float rs = 0.0f;
            #pragma unroll
            for (int j = 0; j < 4; j++) {
                float p = __expf(sv[i][j] - mn);
                sv[i][j] = p;
                rs += p;
            }
            #pragma unroll
            for (int off = 1; off < 16; off <<= 1)
                rs += __shfl_xor_sync(0xffffffffu, rs, off);
            l[i] = l[i] * corr + rs;
            m[i] = mn;
            #pragma unroll
            for (int j = 0; j < 4; j++) o[i][j] *= corr;
            *(float4*)(Ps + (ty * 4 + i) * 68 + tx * 4) =
                make_float4(sv[i][0], sv[i][1], sv[i][2], sv[i][3]);
        }
        __syncthreads();

        // O += P @ V   (output dims = tx*4 + j)
        #pragma unroll 8
        for (int kk = 0; kk < 64; kk++) {
            float pf[4];
            #pragma unroll
            for (int i = 0; i < 4; i++) pf[i] = Ps[(ty * 4 + i) * 68 + kk];
            float4 vv = *(const float4*)(Vs + kk * 68 + tx * 4);
            #pragma unroll
            for (int i = 0; i < 4; i++) {
                o[i][0] = fmaf(pf[i], vv.x, o[i][0]);
                o[i][1] = fmaf(pf[i], vv.y, o[i][1]);
                o[i][2] = fmaf(pf[i], vv.z, o[i][2]);
                o[i][3] = fmaf(pf[i], vv.w, o[i][3]);
            }
        }
    }

    #pragma unroll
    for (int i = 0; i < 4; i++) {
        float inv = 1.0f / l[i];
        float4 r = make_float4(o[i][0] * inv, o[i][1] * inv, o[i][2] * inv, o[i][3] * inv);
        *(float4*)(out + (size_t)(b * SEQ + s0 + ty * 4 + i) * HDIM + h * HD + tx * 4) = r;
    }
}

// ---------------- router / routing machinery ----------------
__global__ void router_kernel(const float* __restrict__ hf, const float* __restrict__ rw) {
    int t = blockIdx.x, tid = threadIdx.x;
    int w = tid >> 5, lane = tid & 31;
    __shared__ float logits[NE];
    float s = 0.0f;
    for (int i = lane; i < HDIM; i += 32)
        s += hf[(size_t)t * HDIM + i] * __ldg(rw + (size_t)i * NE + w);
    #pragma unroll
    for (int o = 16; o; o >>= 1) s += __shfl_xor_sync(0xffffffffu, s, o);
    if (lane == 0) logits[w] = s;
    __syncthreads();
    if (tid == 0) {
        int e0 = 0; float b0 = logits[0];
        #pragma unroll
        for (int e = 1; e < NE; e++) if (logits[e] > b0) { b0 = logits[e]; e0 = e; }
        int e1 = -1; float b1 = -3.0e38f;
        #pragma unroll
        for (int e = 0; e < NE; e++)
            if (e != e0 && logits[e] > b1) { b1 = logits[e]; e1 = e; }
        float w0 = 1.0f / (1.0f + expf(b1 - b0));
        g_tok_e[t * 2 + 0] = e0;
        g_tok_e[t * 2 + 1] = e1;
        g_tok_w[t * 2 + 0] = w0;
        g_tok_w[t * 2 + 1] = 1.0f - w0;
        atomicAdd(&g_cnt[e0], 1);
        atomicAdd(&g_cnt[e1], 1);
    }
}

__global__ void scan_kernel() {
    if (threadIdx.x == 0) {
        int acc = 0;
        for (int e = 0; e < NE; e++) {
            g_off[e] = acc;
            acc += g_cnt[e];
            g_cur[e] = 0;
        }
    }
}

__global__ void assign_gather_kernel(const float* __restrict__ hf) {
    int t = blockIdx.x, tid = threadIdx.x;
    __shared__ int sl[2];
    if (tid < 2) {
        int e = g_tok_e[t * 2 + tid];
        int s = g_off[e] + atomicAdd(&g_cur[e], 1);
        sl[tid] = s;
        g_tok_slot[t * 2 + tid] = s;
    }
    __syncthreads();
    float4 v = ((const float4*)(hf + (size_t)t * HDIM))[tid];
    ((float4*)(g_xg + (size_t)sl[0] * HDIM))[tid] = v;
    ((float4*)(g_xg + (size_t)sl[1] * HDIM))[tid] = v;
}

// silu(g)*u over all SLOTS rows (all rows valid: counts sum to SLOTS exactly)
__global__ void silu_kernel() {
    size_t idx = (size_t)blockIdx.x * 256 + threadIdx.x;  // float4 index
    int row = (int)(idx >> 9);          // INTER/4 = 512 float4 per row
    int jj = (int)(idx & 511) << 2;
    const float* g = g_gu + (size_t)row * (2 * INTER) + jj;
    float4 gv = *(const float4*)g;
    float4 uv = *(const float4*)(g + INTER);
    float4 r;
    r.x = gv.x / (1.0f + expf(-gv.x)) * uv.x;
    r.y = gv.y / (1.0f + expf(-gv.y)) * uv.y;
    r.z = gv.z / (1.0f + expf(-gv.z)) * uv.z;
    r.w = gv.w / (1.0f + expf(-gv.w)) * uv.w;
    *(float4*)(g_act + (size_t)row * INTER + jj) = r;
}

// out[t] += w0*dn[slot0] + w1*dn[slot1]   (deterministic, no atomics)
__global__ void combine_kernel(float* __restrict__ out) {
    int t = blockIdx.x, tid = threadIdx.x;
    int s0 = g_tok_slot[t * 2 + 0], s1 = g_tok_slot[t * 2 + 1];
    float w0 = g_tok_w[t * 2 + 0], w1 = g_tok_w[t * 2 + 1];
    float4 x = ((float4*)(out + (size_t)t * HDIM))[tid];
    float4 a = ((const float4*)(g_dn + (size_t)s0 * HDIM))[tid];
    float4 b = ((const float4*)(g_dn + (size_t)s1 * HDIM))[tid];
    x.x += w0 * a.x + w1 * b.x;
    x.y += w0 * a.y + w1 * b.y;
    x.z += w0 * a.z + w1 * b.z;
    x.w += w0 * a.w + w1 * b.w;
    ((float4*)(out + (size_t)t * HDIM))[tid] = x;
}

// ---------------- launch ----------------
extern "C" void kernel_launch(void* const* d_in, const int* in_sizes, int n_in,
                              void* d_out, int out_size) {
    const float* hidden = (const float*)d_in[0];
    const float* mask   = (const float*)d_in[1];
    const float* ln1    = (const float*)d_in[2];
    const float* ln2    = (const float*)d_in[3];
    const float* qkv_w  = (const float*)d_in[4];
    const float* o_w    = (const float*)d_in[5];
    const float* rt_w   = (const float*)d_in[6];
    const float* gup    = (const float*)d_in[7];
    const float* dwn    = (const float*)d_in[8];
    float* out = (float*)d_out;

    float *hn, *qkvb, *attnb, *hfb, *xg, *gu, *act, *dn;
    cudaGetSymbolAddress((void**)&hn,    g_hn);
    cudaGetSymbolAddress((void**)&qkvb,  g_qkv);
    cudaGetSymbolAddress((void**)&attnb, g_attn);
    cudaGetSymbolAddress((void**)&hfb,   g_hf);
    cudaGetSymbolAddress((void**)&xg,    g_xg);
    cudaGetSymbolAddress((void**)&gu,    g_gu);
    cudaGetSymbolAddress((void**)&act,   g_act);
    cudaGetSymbolAddress((void**)&dn,    g_dn);

    cudaFuncSetAttribute(attn_kernel, cudaFuncAttributeMaxDynamicSharedMemorySize, ATTN_SMEM);

    zero_kernel<<<1, 32>>>();

    // attention block
    rmsnorm_kernel<<<NTOK, 256>>>(hidden, ln1, hn);
    sgemm_plain<<<dim3(TQKV / BN, NTOK / BM), 256>>>(hn, qkv_w, qkvb, TQKV, HDIM, nullptr);
    attn_kernel<<<dim3(SEQ / 64, NBATCH * NH), 256, ATTN_SMEM>>>(qkvb, mask, attnb);
    // o-proj + residual -> out holds x1
    sgemm_plain<<<dim3(HDIM / BN, NTOK / BM), 256>>>(attnb, o_w, out, HDIM, HDIM, hidden);

    // moe block (routed top-2)
    rmsnorm_kernel<<<NTOK, 256>>>(out, ln2, hfb);
    router_kernel<<<NTOK, 256>>>(hfb, rt_w);
    scan_kernel<<<1, 32>>>();
    assign_gather_kernel<<<NTOK, 256>>>(hfb);

    sgemm_moe<<<dim3(2 * INTER / BN, NTOK / BM, NE), 256>>>(
        xg, gup, gu, 2 * INTER, HDIM, (long long)HDIM * 2 * INTER);
    silu_kernel<<<(SLOTS * (INTER / 4)) / 256, 256>>>();
    sgemm_moe<<<dim3(HDIM / BN, NTOK / BM, NE), 256>>>(
        act, dwn, dn, HDIM, INTER, (long long)INTER * HDIM);

    combine_kernel<<<NTOK, 256>>>(out);
}

// round 3
// speedup vs baseline: 1.0016x; 1.0016x over previous
#include <cuda_runtime.h>
#include <math.h>

// ---------------- problem constants ----------------
#define HDIM   1024
#define NH     16
#define HD     64
#define INTER  2048
#define NE     8
#define SEQ    1024
#define NBATCH 4
#define NTOK   4096          // NBATCH*SEQ
#define TQKV   3072          // (NH + 2*NKV)*HD
#define SLOTS  8192          // NTOK * TOPK

// ---------------- scratch (static device globals; no allocation) ----------------
__device__ float g_hn[(size_t)NTOK * HDIM];              // rmsnorm1 out
__device__ float g_qkv[(size_t)NTOK * TQKV];             // qkv proj
__device__ float g_attn[(size_t)NTOK * HDIM];            // attention out (pre o-proj)
__device__ float g_hf[(size_t)NTOK * HDIM];              // rmsnorm2 out
__device__ float g_xg[(size_t)(SLOTS + 128) * HDIM];     // gathered tokens (padded rows)
__device__ float g_gu[(size_t)SLOTS * 2 * INTER];        // gate_up output
__device__ float g_act[(size_t)(SLOTS + 128) * INTER];   // silu(g)*u (padded rows)
__device__ float g_dn[(size_t)SLOTS * HDIM];             // down proj per-slot
__device__ int   g_cnt[NE];
__device__ int   g_off[NE];
__device__ int   g_cur[NE];
__device__ int   g_tok_e[NTOK * 2];
__device__ int   g_tok_slot[NTOK * 2];
__device__ float g_tok_w[NTOK * 2];

// ---------------- small kernels ----------------
__global__ void zero_kernel() {
    if (threadIdx.x < NE) g_cnt[threadIdx.x] = 0;
}

// one block per token, 256 threads, 1 float4 each
__global__ void rmsnorm_kernel(const float* __restrict__ x,
                               const float* __restrict__ w,
                               float* __restrict__ y) {
    int t = blockIdx.x, tid = threadIdx.x;
    const float4 v = ((const float4*)(x + (size_t)t * HDIM))[tid];
    float ss = v.x * v.x + v.y * v.y + v.z * v.z + v.w * v.w;
    __shared__ float red[8];
    #pragma unroll
    for (int o = 16; o; o >>= 1) ss += __shfl_xor_sync(0xffffffffu, ss, o);
    if ((tid & 31) == 0) red[tid >> 5] = ss;
    __syncthreads();
    if (tid < 8) {
        float s2 = red[tid];
        #pragma unroll
        for (int o = 4; o; o >>= 1) s2 += __shfl_xor_sync(0xffu, s2, o);
        if (tid == 0) red[0] = s2;
    }
    __syncthreads();
    float inv = rsqrtf(red[0] * (1.0f / HDIM) + 1e-6f);
    const float4 wv = ((const float4*)w)[tid];
    float4 r = make_float4(v.x * inv * wv.x, v.y * inv * wv.y,
                           v.z * inv * wv.z, v.w * inv * wv.w);
    ((float4*)(y + (size_t)t * HDIM))[tid] = r;
}

// ---------------- SGEMM 128x128x8, 8x8 per thread, 256 threads ----------------
#define BM 128
#define BN 128
#define BKC 8

__device__ __forceinline__ void sgemm_body(
    const float* __restrict__ A, const float* __restrict__ B, float* __restrict__ C,
    int N, int K, int Meff, const float* __restrict__ res)
{
    __shared__ float As[BKC][BM];
    __shared__ float Bs[BKC][BN];
    const int tid = threadIdx.x;
    const int bx = blockIdx.x, by = blockIdx.y;
    const int aRow = tid >> 1;
    const int aCol = (tid & 1) << 2;
    const int bRow = tid >> 5;
    const int bCol = (tid & 31) << 2;
    const int tx = tid & 15, ty = tid >> 4;

    const float* Ap = A + (size_t)(by * BM + aRow) * K + aCol;
    const float* Bp = B + (size_t)bRow * N + bx * BN + bCol;

    float acc[8][8];
    #pragma unroll
    for (int i = 0; i < 8; i++)
        #pragma unroll
        for (int j = 0; j < 8; j++) acc[i][j] = 0.0f;

    for (int k0 = 0; k0 < K; k0 += BKC) {
        float4 a4 = *(const float4*)Ap;
        float4 b4 = *(const float4*)Bp;
        As[aCol + 0][aRow] = a4.x;
        As[aCol + 1][aRow] = a4.y;
        As[aCol + 2][aRow] = a4.z;
        As[aCol + 3][aRow] = a4.w;
        *(float4*)(&Bs[bRow][bCol]) = b4;
        __syncthreads();
        #pragma unroll
        for (int kk = 0; kk < BKC; kk++) {
            float ar[8], br[8];
            *(float4*)(ar)     = *(const float4*)(&As[kk][ty * 4]);
            *(float4*)(ar + 4) = *(const float4*)(&As[kk][ty * 4 + 64]);
            *(float4*)(br)     = *(const float4*)(&Bs[kk][tx * 4]);
            *(float4*)(br + 4) = *(const float4*)(&Bs[kk][tx * 4 + 64]);
            #pragma unroll
            for (int i = 0; i < 8; i++)
                #pragma unroll
                for (int j = 0; j < 8; j++)
                    acc[i][j] = fmaf(ar[i], br[j], acc[i][j]);
        }
        __syncthreads();
        Ap += BKC;
        Bp += (size_t)BKC * N;
    }

    #pragma unroll
    for (int i = 0; i < 8; i++) {
        int r = by * BM + ty * 4 + ((i < 4) ? i : (64 + i - 4));
        if (r >= Meff) continue;
        #pragma unroll
        for (int jh = 0; jh < 2; jh++) {
            int c = bx * BN + tx * 4 + jh * 64;
            float4 v = make_float4(acc[i][jh * 4 + 0], acc[i][jh * 4 + 1],
                                   acc[i][jh * 4 + 2], acc[i][jh * 4 + 3]);
            if (res) {
                const float4 rv = *(const float4*)(res + (size_t)r * N + c);
                v.x += rv.x; v.y += rv.y; v.z += rv.z; v.w += rv.w;
            }
            *(float4*)(C + (size_t)r * N + c) = v;
        }
    }
}

__global__ void sgemm_plain(const float* __restrict__ A, const float* __restrict__ B,
                            float* __restrict__ C, int N, int K,
                            const float* __restrict__ res) {
    sgemm_body(A, B, C, N, K, 1 << 30, res);
}

// batched expert GEMM: blockIdx.z = expert; rows start at g_off[e], count g_cnt[e]
__global__ void sgemm_moe(const float* __restrict__ A0, const float* __restrict__ B0,
                          float* __restrict__ C0, int N, int K, long long strideB) {
    int e = blockIdx.z;
    int Meff = g_cnt[e];
    if ((int)blockIdx.y * BM >= Meff) return;
    int off = g_off[e];
    const float* A = A0 + (size_t)off * K;
    const float* B = B0 + (size_t)e * strideB;
    float* C = C0 + (size_t)off * N;
    sgemm_body(A, B, C, N, K, Meff, nullptr);
}

// ---------------- flash attention (fp32) ----------------
// grid: (SEQ/64, NBATCH*NH). block: 256 (16x16). 64q x 64k tiles, HD=64.
#define ATTN_SMEM ((64*64 + 64*65 + 64*68 + 64*68) * 4)

__global__ void attn_kernel(const float* __restrict__ qkv,
                            const float* __restrict__ mask,
                            float* __restrict__ out) {
    extern __shared__ float sm[];
    float* Qs = sm;                 // [64][64]
    float* Kt = Qs + 64 * 64;       // [64 d][65]  (d-major)
    float* Vs = Kt + 64 * 65;       // [64 kv][68]
    float* Ps = Vs + 64 * 68;       // [64 q][68]

    const int tid = threadIdx.x;
    const int qb = blockIdx.x;
    const int bh = blockIdx.y;
    const int b = bh >> 4, h = bh & 15;
    const int s0 = qb * 64;
    const int tx = tid & 15, ty = tid >> 4;

    // load + pre-scale Q (1/sqrt(64) = 0.125)
    for (int idx = tid; idx < 64 * 16; idx += 256) {
        int r = idx >> 4, c4 = (idx & 15) << 2;
        float4 v = *(const float4*)(qkv + (size_t)(b * SEQ + s0 + r) * TQKV + h * HD + c4);
        v.x *= 0.125f; v.y *= 0.125f; v.z *= 0.125f; v.w *= 0.125f;
        *(float4*)(Qs + r * 64 + c4) = v;
    }

    float m[4], l[4], o[4][4];
    #pragma unroll
    for (int i = 0; i < 4; i++) {
        m[i] = -3.0e38f; l[i] = 0.0f;
        #pragma unroll
        for (int j = 0; j < 4; j++) o[i][j] = 0.0f;
    }

    for (int kt = 0; kt < SEQ / 64; kt++) {
        __syncthreads();   // previous tile's Ps/Vs reads done; Q load done (iter 0)
        const int k0 = kt * 64;
        for (int idx = tid; idx < 64 * 16; idx += 256) {
            int r = idx >> 4, c4 = (idx & 15) << 2;
            const float* src = qkv + (size_t)(b * SEQ + k0 + r) * TQKV + NH * HD + h * HD + c4;
            float4 kv = *(const float4*)src;
            Kt[(c4 + 0) * 65 + r] = kv.x;
            Kt[(c4 + 1) * 65 + r] = kv.y;
            Kt[(c4 + 2) * 65 + r] = kv.z;
            Kt[(c4 + 3) * 65 + r] = kv.w;
            float4 vv = *(const float4*)(src + NH * HD);   // v block is +1024 after k start
            *(float4*)(Vs + r * 68 + c4) = vv;
        }
        __syncthreads();

        // scores: rows ty*4+i, cols tx*4+j, init with mask
        float sv[4][4];
        #pragma unroll
        for (int i = 0; i < 4; i++) {
            float4 mk = *(const float4*)(mask + (size_t)(s0 + ty * 4 + i) * SEQ + k0 + tx * 4);
            sv[i][0] = mk.x; sv[i][1] = mk.y; sv[i][2] = mk.z; sv[i][3] = mk.w;
        }
        #pragma unroll 8
        for (int kk = 0; kk < 64; kk++) {
            float qf[4], kf[4];
            #pragma unroll
            for (int i = 0; i < 4; i++) qf[i] = Qs[(ty * 4 + i) * 64 + kk];
            #pragma unroll
            for (int j = 0; j < 4; j++) kf[j] = Kt[kk * 65 + tx * 4 + j];
            #pragma unroll
            for (int i = 0; i < 4; i++)
                #pragma unroll
                for (int j = 0; j < 4; j++)
                    sv[i][j] = fmaf(qf[i], kf[j], sv[i][j]);
        }

        // online softmax per row (reduce over 16-lane tx groups)
        #pragma unroll
        for (int i = 0; i < 4; i++) {
            float tm = fmaxf(fmaxf(sv[i][0], sv[i][1]), fmaxf(sv[i][2], sv[i][3]));
            #pragma unroll
            for (int off = 1; off < 16; off <<= 1)
                tm = fmaxf(tm, __shfl_xor_sync(0xffffffffu, tm, off));
            float mn = fmaxf(m[i], tm);
            float corr = __expf(m[i] - mn);
            float rs = 0.0f;
            #pragma unroll
            for (int j = 0; j < 4; j++) {
                float p = __expf(sv[i][j] - mn);
                sv[i][j] = p;
                rs += p;
            }
            #pragma unroll
            for (int off = 1; off < 16; off <<= 1)
                rs += __shfl_xor_sync(0xffffffffu, rs, off);
            l[i] = l[i] * corr + rs;
            m[i] = mn;
            #pragma unroll
            for (int j = 0; j < 4; j++) o[i][j] *= corr;
            *(float4*)(Ps + (ty * 4 + i) * 68 + tx * 4) =
                make_float4(sv[i][0], sv[i][1], sv[i][2], sv[i][3]);
        }
        __syncthreads();

        // O += P @ V   (output dims = tx*4 + j)
        #pragma unroll 8
        for (int kk = 0; kk < 64; kk++) {
            float pf[4];
            #pragma unroll
            for (int i = 0; i < 4; i++) pf[i] = Ps[(ty * 4 + i) * 68 + kk];
            float4 vv = *(const float4*)(Vs + kk * 68 + tx * 4);
            #pragma unroll
            for (int i = 0; i < 4; i++) {
                o[i][0] = fmaf(pf[i], vv.x, o[i][0]);
                o[i][1] = fmaf(pf[i], vv.y, o[i][1]);
                o[i][2] = fmaf(pf[i], vv.z, o[i][2]);
                o[i][3] = fmaf(pf[i], vv.w, o[i][3]);
            }
        }
    }

    #pragma unroll
    for (int i = 0; i < 4; i++) {
        float inv = 1.0f / l[i];
        float4 r = make_float4(o[i][0] * inv, o[i][1] * inv, o[i][2] * inv, o[i][3] * inv);
        *(float4*)(out + (size_t)(b * SEQ + s0 + ty * 4 + i) * HDIM + h * HD + tx * 4) = r;
    }
}

// ---------------- router / routing machinery ----------------
__global__ void router_kernel(const float* __restrict__ hf, const float* __restrict__ rw) {
    int t = blockIdx.x, tid = threadIdx.x;
    int w = tid >> 5, lane = tid & 31;
    __shared__ float logits[NE];
    float s = 0.0f;
    for (int i = lane; i < HDIM; i += 32)
        s += hf[(size_t)t * HDIM + i] * __ldg(rw + (size_t)i * NE + w);
    #pragma unroll
    for (int o = 16; o; o >>= 1) s += __shfl_xor_sync(0xffffffffu, s, o);
    if (lane == 0) logits[w] = s;
    __syncthreads();
    if (tid == 0) {
        int e0 = 0; float b0 = logits[0];
        #pragma unroll
        for (int e = 1; e < NE; e++) if (logits[e] > b0) { b0 = logits[e]; e0 = e; }
        int e1 = -1; float b1 = -3.0e38f;
        #pragma unroll
        for (int e = 0; e < NE; e++)
            if (e != e0 && logits[e] > b1) { b1 = logits[e]; e1 = e; }
        float w0 = 1.0f / (1.0f + expf(b1 - b0));
        g_tok_e[t * 2 + 0] = e0;
        g_tok_e[t * 2 + 1] = e1;
        g_tok_w[t * 2 + 0] = w0;
        g_tok_w[t * 2 + 1] = 1.0f - w0;
        atomicAdd(&g_cnt[e0], 1);
        atomicAdd(&g_cnt[e1], 1);
    }
}

__global__ void scan_kernel() {
    if (threadIdx.x == 0) {
        int acc = 0;
        for (int e = 0; e < NE; e++) {
            g_off[e] = acc;
            acc += g_cnt[e];
            g_cur[e] = 0;
        }
    }
}

__global__ void assign_gather_kernel(const float* __restrict__ hf) {
    int t = blockIdx.x, tid = threadIdx.x;
    __shared__ int sl[2];
    if (tid < 2) {
        int e = g_tok_e[t * 2 + tid];
        int s = g_off[e] + atomicAdd(&g_cur[e], 1);
        sl[tid] = s;
        g_tok_slot[t * 2 + tid] = s;
    }
    __syncthreads();
    float4 v = ((const float4*)(hf + (size_t)t * HDIM))[tid];
    ((float4*)(g_xg + (size_t)sl[0] * HDIM))[tid] = v;
    ((float4*)(g_xg + (size_t)sl[1] * HDIM))[tid] = v;
}

// silu(g)*u over all SLOTS rows (all rows valid: counts sum to SLOTS exactly)
__global__ void silu_kernel() {
    size_t idx = (size_t)blockIdx.x * 256 + threadIdx.x;  // float4 index
    int row = (int)(idx >> 9);          // INTER/4 = 512 float4 per row
    int jj = (int)(idx & 511) << 2;
    const float* g = g_gu + (size_t)row * (2 * INTER) + jj;
    float4 gv = *(const float4*)g;
    float4 uv = *(const float4*)(g + INTER);
    float4 r;
    r.x = gv.x / (1.0f + expf(-gv.x)) * uv.x;
    r.y = gv.y / (1.0f + expf(-gv.y)) * uv.y;
    r.z = gv.z / (1.0f + expf(-gv.z)) * uv.z;
    r.w = gv.w / (1.0f + expf(-gv.w)) * uv.w;
    *(float4*)(g_act + (size_t)row * INTER + jj) = r;
}

// out[t] += w0*dn[slot0] + w1*dn[slot1]   (deterministic, no atomics)
__global__ void combine_kernel(float* __restrict__ out) {
    int t = blockIdx.x, tid = threadIdx.x;
    int s0 = g_tok_slot[t * 2 + 0], s1 = g_tok_slot[t * 2 + 1];
    float w0 = g_tok_w[t * 2 + 0], w1 = g_tok_w[t * 2 + 1];
    float4 x = ((float4*)(out + (size_t)t * HDIM))[tid];
    float4 a = ((const float4*)(g_dn + (size_t)s0 * HDIM))[tid];
    float4 b = ((const float4*)(g_dn + (size_t)s1 * HDIM))[tid];
    x.x += w0 * a.x + w1 * b.x;
    x.y += w0 * a.y + w1 * b.y;
    x.z += w0 * a.z + w1 * b.z;
    x.w += w0 * a.w + w1 * b.w;
    ((float4*)(out + (size_t)t * HDIM))[tid] = x;
}

// ---------------- launch ----------------
extern "C" void kernel_launch(void* const* d_in, const int* in_sizes, int n_in,
                              void* d_out, int out_size) {
    const float* hidden = (const float*)d_in[0];
    const float* mask   = (const float*)d_in[1];
    const float* ln1    = (const float*)d_in[2];
    const float* ln2    = (const float*)d_in[3];
    const float* qkv_w  = (const float*)d_in[4];
    const float* o_w    = (const float*)d_in[5];
    const float* rt_w   = (const float*)d_in[6];
    const float* gup    = (const float*)d_in[7];
    const float* dwn    = (const float*)d_in[8];
    float* out = (float*)d_out;

    float *hn, *qkvb, *attnb, *hfb, *xg, *gu, *act, *dn;
    cudaGetSymbolAddress((void**)&hn,    g_hn);
    cudaGetSymbolAddress((void**)&qkvb,  g_qkv);
    cudaGetSymbolAddress((void**)&attnb, g_attn);
    cudaGetSymbolAddress((void**)&hfb,   g_hf);
    cudaGetSymbolAddress((void**)&xg,    g_xg);
    cudaGetSymbolAddress((void**)&gu,    g_gu);
    cudaGetSymbolAddress((void**)&act,   g_act);
    cudaGetSymbolAddress((void**)&dn,    g_dn);

    cudaFuncSetAttribute(attn_kernel, cudaFuncAttributeMaxDynamicSharedMemorySize, ATTN_SMEM);

    zero_kernel<<<1, 32>>>();

    // attention block
    rmsnorm_kernel<<<NTOK, 256>>>(hidden, ln1, hn);
    sgemm_plain<<<dim3(TQKV / BN, NTOK / BM), 256>>>(hn, qkv_w, qkvb, TQKV, HDIM, nullptr);
    attn_kernel<<<dim3(SEQ / 64, NBATCH * NH), 256, ATTN_SMEM>>>(qkvb, mask, attnb);
    // o-proj + residual -> out holds x1
    sgemm_plain<<<dim3(HDIM / BN, NTOK / BM), 256>>>(attnb, o_w, out, HDIM, HDIM, hidden);

    // moe block (routed top-2)
    rmsnorm_kernel<<<NTOK, 256>>>(out, ln2, hfb);
    router_kernel<<<NTOK, 256>>>(hfb, rt_w);
    scan_kernel<<<1, 32>>>();
    assign_gather_kernel<<<NTOK, 256>>>(hfb);

    sgemm_moe<<<dim3(2 * INTER / BN, NTOK / BM, NE), 256>>>(
        xg, gup, gu, 2 * INTER, HDIM, (long long)HDIM * 2 * INTER);
    silu_kernel<<<(SLOTS * (INTER / 4)) / 256, 256>>>();
    sgemm_moe<<<dim3(HDIM / BN, NTOK / BM, NE), 256>>>(
        act, dwn, dn, HDIM, INTER, (long long)INTER * HDIM);

    combine_kernel<<<NTOK, 256>>>(out);
}